// round 14
// baseline (speedup 1.0000x reference)
#include <cuda_runtime.h>
#include <cuda_fp16.h>
#include <cstdint>

// lstm_model_8873402433789 R14 — warp-autonomous fp16 mma.sync LSTM.
// Each warp owns 8 rows x ALL 32 units (8 m-tiles, 24 MMAs/step): h is
// warp-private -> NO barriers in the 200-step loop (syncwarp only).
// Sigmoid: tanh.approx.f16x2 on column pairs, 0.5 folded into i/f/o weights.
// 256 CTAs x 128 thr (4 warps), 1024 independent warps.
// R14 fix: HSTR 36 -> 40 halfs (ldmatrix row pointers must be 16B-aligned).

#define TT 200
#define DD 60
#define CROWS 32    // rows per CTA (4 warps x 8)
#define WSTR 56     // weight row stride (halfs), 112B = 7x16B
#define HSTR 40     // h row stride (halfs), 80B = 5x16B (16B-aligned rows!)
#define XSTR 40     // x row stride: buf0 k0-15, buf1 k16-31

static __device__ __forceinline__ uint32_t s2u(const void* p) {
    uint32_t a;
    asm("{ .reg .u64 t; cvta.to.shared.u64 t, %1; cvt.u32.u64 %0, t; }"
        : "=r"(a) : "l"(p));
    return a;
}
static __device__ __forceinline__ uint32_t hpack(float lo, float hi) {
    __half2 t = __floats2half2_rn(lo, hi);   // x = lo, y = hi
    return *(uint32_t*)&t;
}
static __device__ __forceinline__ __half2 tanh2(uint32_t g2) {
    uint32_t r;
    asm("tanh.approx.f16x2 %0, %1;" : "=r"(r) : "r"(g2));
    return *(__half2*)&r;
}
static __device__ __forceinline__ void ldsm4(uint32_t* r, uint32_t addr) {
    asm volatile("ldmatrix.sync.aligned.m8n8.x4.shared.b16 {%0,%1,%2,%3}, [%4];"
                 : "=r"(r[0]), "=r"(r[1]), "=r"(r[2]), "=r"(r[3]) : "r"(addr));
}
static __device__ __forceinline__ void ldsm2(uint32_t* r, uint32_t addr) {
    asm volatile("ldmatrix.sync.aligned.m8n8.x2.shared.b16 {%0,%1}, [%2];"
                 : "=r"(r[0]), "=r"(r[1]) : "r"(addr));
}
static __device__ __forceinline__ void mma16816(float* d, const uint32_t* a,
                                                const uint32_t* b) {
    asm volatile(
        "mma.sync.aligned.m16n8k16.row.col.f32.f16.f16.f32 "
        "{%0,%1,%2,%3}, {%4,%5,%6,%7}, {%8,%9}, {%0,%1,%2,%3};"
        : "+f"(d[0]), "+f"(d[1]), "+f"(d[2]), "+f"(d[3])
        : "r"(a[0]), "r"(a[1]), "r"(a[2]), "r"(a[3]), "r"(b[0]), "r"(b[1]));
}

__global__ void __launch_bounds__(128, 2) lstm_auto_kernel(
    const float* __restrict__ x,  const float* __restrict__ W,
    const float* __restrict__ U,  const float* __restrict__ b,
    const float* __restrict__ W1, const float* __restrict__ b1,
    const float* __restrict__ W2, const float* __restrict__ b2,
    float* __restrict__ out)
{
    __shared__ __align__(16) __half wsm[128 * WSTR];      // weights / h32 (heads)
    __shared__ __align__(16) __half hsm[4 * 2 * 8 * HSTR];// per-warp h, dbl buf
    __shared__ __align__(16) __half xpr[4 * 8 * XSTR];    // per-warp x, dbl buf

    const int tid = threadIdx.x;
    const int l   = tid & 31;
    const int w   = tid >> 5;        // 0..3
    const int gid = l >> 2, tig = l & 3;

    // ---- weights fp16, 0.5 folded into i/f/o gates (c gates 64-95 unscaled)
    for (int idx = tid; idx < 128 * 48; idx += 128) {
        int g = idx / 48, k = idx - g * 48;
        float src = (k < 32) ? U[k * 128 + g] : W[(k - 32) * 128 + g];
        float sc  = (g >= 64 && g < 96) ? 1.0f : 0.5f;
        wsm[g * WSTR + k] = __float2half_rn(src * sc);
    }
    __syncthreads();

    // ---- A fragments for ALL 8 m-tiles: afr[mt][ks 0,1 = h k; 2 = x k]
    const uint32_t wsmu = s2u(wsm);
    uint32_t afr[8][3][4];
    {
        int laneRow = (l & 7) + 8 * ((l >> 3) & 1);
        int laneK   = 8 * (l >> 4);
#pragma unroll
        for (int mt = 0; mt < 8; ++mt)
#pragma unroll
            for (int ks = 0; ks < 3; ++ks)
                ldsm4(afr[mt][ks], wsmu + ((16 * mt + laneRow) * WSTR + 16 * ks + laneK) * 2);
    }
    float bv[8][2];
#pragma unroll
    for (int mt = 0; mt < 8; ++mt) {
        float sc = (mt == 4 || mt == 5) ? 1.0f : 0.5f;   // c-gates unscaled
        bv[mt][0] = sc * b[16 * mt + gid];
        bv[mt][1] = sc * b[16 * mt + gid + 8];
    }

    // ---- per-warp h region (dbl buffered), zero both bufs
    __half* hw = hsm + w * (2 * 8 * HSTR);
    for (int idx = l; idx < 2 * 8 * HSTR; idx += 32)
        hw[idx] = __float2half_rn(0.0f);

    // ---- stage x(0) (own 8 rows), prefetch x(1)
    const int prow = l >> 2, pseg = l & 3;   // 8 rows x 4 float4-segs
    const float4* xg = (const float4*)(x +
        ((size_t)blockIdx.x * CROWS + w * 8 + prow) * (TT * 16)) + pseg;
    __half* xmy = xpr + (w * 8 + prow) * XSTR;
    {
        float4 v = xg[0];
        *(uint2*)(xmy + pseg * 4) = make_uint2(hpack(v.x, v.y), hpack(v.z, v.w));
    }
    float4 pf = xg[4];
    __syncwarp();

    const uint32_t hwu = s2u(hw);
    const uint32_t xbu = s2u(xpr + w * 8 * XSTR);
    const int lr8 = l & 7;

    const uint32_t xfoff = (lr8 * XSTR + 8 * ((l >> 3) & 1)) * 2;
    uint32_t xf[2];
    ldsm2(xf, xbu + xfoff);

    float cst[2][2][2], hrg[2][2][2];   // [ug][rh][q]
#pragma unroll
    for (int i = 0; i < 2; ++i)
#pragma unroll
        for (int j = 0; j < 2; ++j)
#pragma unroll
            for (int k = 0; k < 2; ++k) { cst[i][j][k] = 0.0f; hrg[i][j][k] = 0.0f; }

#pragma unroll 1
    for (int t = 0; t < TT; ++t) {
        const int p = t & 1, pn = p ^ 1;

        // ---- x-MMAs (xf from previous iteration)
        float dac[8][4];
#pragma unroll
        for (int mt = 0; mt < 8; ++mt) {
            dac[mt][0] = bv[mt][0]; dac[mt][1] = bv[mt][0];
            dac[mt][2] = bv[mt][1]; dac[mt][3] = bv[mt][1];
        }
#pragma unroll
        for (int mt = 0; mt < 8; ++mt)
            mma16816(dac[mt], afr[mt][2], xf);           // W . x

        // ---- own h(t) (stores from prev iter) -> fragment -> h-MMAs
        __syncwarp();
        uint32_t bh[4];
        ldsm4(bh, hwu + (p * (8 * HSTR) + lr8 * HSTR + 8 * (l >> 3)) * 2);
#pragma unroll
        for (int mt = 0; mt < 8; ++mt) {
            mma16816(dac[mt], afr[mt][0], &bh[0]);       // U . h k0-15
            mma16816(dac[mt], afr[mt][1], &bh[2]);       // U . h k16-31
        }

        // ---- stage x(t+1); prefetch x(t+2); reload xf
        {
            *(uint2*)(xmy + pn * 16 + pseg * 4) =
                make_uint2(hpack(pf.x, pf.y), hpack(pf.z, pf.w));
            int tn = (t + 2 < TT) ? t + 2 : TT - 1;
            pf = xg[tn * 4];
            __syncwarp();
            ldsm2(xf, xbu + pn * 32 + xfoff);
        }

        // ---- update: f16x2 tanh sigmoid (gates pre-halved), c fp32
#pragma unroll
        for (int ug = 0; ug < 2; ++ug)
#pragma unroll
            for (int rh = 0; rh < 2; ++rh) {
                const int e0 = 2 * rh;
                __half2 ti = tanh2(hpack(dac[ug][e0],     dac[ug][e0 + 1]));
                __half2 tf = tanh2(hpack(dac[2 + ug][e0], dac[2 + ug][e0 + 1]));
                __half2 to = tanh2(hpack(dac[6 + ug][e0], dac[6 + ug][e0 + 1]));
                const int u = 16 * ug + 8 * rh + gid;
#pragma unroll
                for (int q = 0; q < 2; ++q) {
                    float tiq = q ? __high2float(ti) : __low2float(ti);
                    float tfq = q ? __high2float(tf) : __low2float(tf);
                    float toq = q ? __high2float(to) : __low2float(to);
                    float cc  = fmaxf(dac[4 + ug][e0 + q], 0.0f);
                    float co  = cst[ug][rh][q];
                    float c   = 0.5f * (fmaf(tfq, co, co) + fmaf(tiq, cc, cc));
                    cst[ug][rh][q] = c;
                    float hv  = fmaf(0.5f, toq, 0.5f) * fmaxf(c, 0.0f);
                    hrg[ug][rh][q] = hv;
                    hw[pn * (8 * HSTR) + (2 * tig + q) * HSTR + u] =
                        __float2half_rn(hv);
                }
            }
        // next iteration's syncwarp covers h visibility (warp-private)
    }

    // ---- output heads: reuse wsm as fp32 h buffer [32 rows][32 units]
    __syncthreads();
    float* h32 = (float*)wsm;
#pragma unroll
    for (int ug = 0; ug < 2; ++ug)
#pragma unroll
        for (int rh = 0; rh < 2; ++rh) {
            const int u = 16 * ug + 8 * rh + gid;
#pragma unroll
            for (int q = 0; q < 2; ++q)
                h32[(w * 8 + 2 * tig + q) * 32 + u] = hrg[ug][rh][q];
        }
    __syncthreads();

    for (int idx = tid; idx < CROWS * DD; idx += 128) {
        int rr = idx / DD, d = idx - rr * DD;
        const float* hr = h32 + rr * 32;
        float aL = b1[d], aA = b2[d];
#pragma unroll
        for (int u = 0; u < 32; ++u) {
            float hu = hr[u];
            aL = fmaf(hu, W1[u * DD + d], aL);
            aA = fmaf(hu, W2[u * DD + d], aA);
        }
        size_t grow = (size_t)blockIdx.x * CROWS + rr;
        out[grow * DD + d] = aL;
        out[(8192 + grow) * DD + d] = aA;
    }
}

extern "C" void kernel_launch(void* const* d_in, const int* in_sizes, int n_in,
                              void* d_out, int out_size) {
    const float* x  = (const float*)d_in[0];
    const float* W  = (const float*)d_in[1];
    const float* U  = (const float*)d_in[2];
    const float* b  = (const float*)d_in[3];
    const float* W1 = (const float*)d_in[4];
    const float* b1 = (const float*)d_in[5];
    const float* W2 = (const float*)d_in[6];
    const float* b2 = (const float*)d_in[7];
    float* out = (float*)d_out;

    // 8192 rows / 32 per CTA = 256 CTAs, 128 threads (4 autonomous warps)
    lstm_auto_kernel<<<256, 128>>>(x, W, U, b, W1, b1, W2, b2, out);
}